// round 4
// baseline (speedup 1.0000x reference)
#include <cuda_runtime.h>
#include <cstdint>

// Problem constants (asserted by reference):
//   x: [8, 128, 128, 128]  (B, D, H, W), HW = 16384, NPIX = 131072
//   C = 128 classes, M = 1, NEG = 3  -> 512 prototypes total
// Output tuple flattened in order:
//   cls_score  [8,128,128,128]      @ 0          (16777216)
//   distances  [8,128,1,128,128]    @ 16777216   (16777216)
//   distances_neg [8,128,3,128,128] @ 33554432   (50331648)
//   probs_ori  [8,128,128,128]      @ 83886080   (16777216)

typedef unsigned long long ull;

// Prototype matrix, pre-transposed per 128-proto chunk: g_PT[chunk*16384 + d*128 + cLocal]
// chunk 0..2 = negative prototypes n=0..2 (per class), chunk 3 = positive prototypes.
__device__ float g_PT[4 * 128 * 128];

// ---------------------------------------------------------------------------
// Prep: normalize reps, build negative prototypes, store transposed.
// grid = 128 (one CTA per class), block = 128 (one thread per channel d)
// ---------------------------------------------------------------------------
__global__ void dml_prep(const float* __restrict__ reps_w,
                         const float* __restrict__ fc_w,
                         const float* __restrict__ fc_b) {
    __shared__ float repn[128];
    __shared__ float red[128];
    const int c = blockIdx.x;
    const int d = threadIdx.x;

    float w = reps_w[c * 128 + d];
    red[d] = w * w;
    __syncthreads();
    for (int s = 64; s > 0; s >>= 1) { if (d < s) red[d] += red[d + s]; __syncthreads(); }
    float S = red[0];
    __syncthreads();
    float rn = w / fmaxf(sqrtf(S), 1e-12f);
    repn[d] = rn;
    g_PT[3 * 16384 + d * 128 + c] = rn;   // positive prototypes, chunk 3
    __syncthreads();

    for (int n = 0; n < 3; n++) {
        const float* wr = fc_w + (size_t)(n * 128 + d) * 128;
        float a = fc_b[n * 128 + d];
        #pragma unroll 8
        for (int k = 0; k < 128; k++) a += repn[k] * wr[k];
        float v = a + rn;                 // neg_off + reps_flat
        red[d] = v * v;
        __syncthreads();
        for (int s = 64; s > 0; s >>= 1) { if (d < s) red[d] += red[d + s]; __syncthreads(); }
        float S2 = red[0];
        __syncthreads();
        g_PT[n * 16384 + d * 128 + c] = v / fmaxf(sqrtf(S2), 1e-12f);
    }
}

// ---------------------------------------------------------------------------
// Packed fp32x2 helpers (Blackwell FFMA2 — only reachable via PTX)
// ---------------------------------------------------------------------------
__device__ __forceinline__ ull pk(float v) {
    ull r; asm("mov.b64 %0, {%1,%1};" : "=l"(r) : "f"(v)); return r;
}
__device__ __forceinline__ void fma2(ull& d, ull a, ull b) {
    asm("fma.rn.f32x2 %0, %1, %2, %0;" : "+l"(d) : "l"(a), "l"(b));
}
__device__ __forceinline__ void unpk(ull v, float& lo, float& hi) {
    asm("mov.b64 {%0,%1}, %2;" : "=f"(lo), "=f"(hi) : "l"(v));
}
union F4U { float4 f; ull u[2]; };

// ---------------------------------------------------------------------------
// Main fused kernel.
// grid = 2048 (8 batches * 256 pixel-tiles), block = 128 threads.
// Each CTA: 64 contiguous hw pixels of one batch image.
// Thread tile: 8 px * 8 protos (protos packed pairwise for f32x2).
// smem: xs[128k][64px] | pt[128k][128proto] | dbuf[128c][64px] | mn[128c][64px]
//       | rs[64] | part[128]   (total 41152 floats = 164608 B)
// ---------------------------------------------------------------------------
__global__ __launch_bounds__(128, 1)
void dml_main(const float* __restrict__ x, float* __restrict__ out) {
    extern __shared__ float sm[];
    float* xs   = sm;            // 8192
    float* pt   = sm + 8192;     // 16384
    float* dbuf = sm + 24576;    // 8192
    float* mn   = sm + 32768;    // 8192
    float* rs   = sm + 40960;    // 64
    float* part = sm + 41024;    // 128

    const int tid = threadIdx.x;
    const int b   = blockIdx.x >> 8;
    const int hw0 = (blockIdx.x & 255) << 6;
    const float* xb = x + ((size_t)b * 128) * 16384 + hw0;

    // Load x tile: xs[d][px] — contiguous px dimension, coalesced.
    for (int i = tid; i < 8192; i += 128)
        xs[i] = xb[(size_t)(i >> 6) * 16384 + (i & 63)];
    __syncthreads();

    // Per-pixel L2 norm, fold into xs (emb = x / max(||x||, eps)).
    {
        int p = tid & 63, h = tid >> 6;
        float s = 0.f;
        #pragma unroll 8
        for (int d = 0; d < 64; d++) { float v = xs[(h * 64 + d) * 64 + p]; s += v * v; }
        part[tid] = s;
    }
    __syncthreads();
    if (tid < 64) rs[tid] = 1.0f / fmaxf(sqrtf(part[tid] + part[tid + 64]), 1e-12f);
    __syncthreads();
    for (int i = tid; i < 8192; i += 128) xs[i] *= rs[i & 63];

    const int tx = tid & 7;    // pixel-group  (8 px each)
    const int ty = tid >> 3;   // proto-group  (8 protos each)
    const float4* xs4 = (const float4*)xs;
    const float4* pt4 = (const float4*)pt;

    for (int cc = 0; cc < 4; cc++) {
        __syncthreads();   // protect pt + dbuf reuse
        {
            const float4* gp = (const float4*)(g_PT + cc * 16384);
            float4* w4 = (float4*)pt;
            for (int i = tid; i < 4096; i += 128) w4[i] = gp[i];
        }
        __syncthreads();

        ull acc[8][4];
        #pragma unroll
        for (int i = 0; i < 8; i++)
            #pragma unroll
            for (int j = 0; j < 4; j++) acc[i][j] = 0ULL;

        #pragma unroll 4
        for (int k = 0; k < 128; k++) {
            float4 xa = xs4[k * 16 + tx * 2];
            float4 xc = xs4[k * 16 + tx * 2 + 1];
            F4U p0, p1;
            p0.f = pt4[k * 32 + ty * 2];
            p1.f = pt4[k * 32 + ty * 2 + 1];
            ull xq[8] = { pk(xa.x), pk(xa.y), pk(xa.z), pk(xa.w),
                          pk(xc.x), pk(xc.y), pk(xc.z), pk(xc.w) };
            #pragma unroll
            for (int i = 0; i < 8; i++) {
                fma2(acc[i][0], p0.u[0], xq[i]);
                fma2(acc[i][1], p0.u[1], xq[i]);
                fma2(acc[i][2], p1.u[0], xq[i]);
                fma2(acc[i][3], p1.u[1], xq[i]);
            }
        }

        if (cc < 3) {
            // Negative chunk: distances_neg + running min.
            #pragma unroll
            for (int i = 0; i < 8; i++) {
                int p = tx * 8 + i;
                #pragma unroll
                for (int j = 0; j < 4; j++) {
                    float lo, hi; unpk(acc[i][j], lo, hi);
                    int c0 = ty * 8 + 2 * j;
                    float da = sqrtf(fmaxf(2.f - 2.f * lo, 1e-12f));
                    float db = sqrtf(fmaxf(2.f - 2.f * hi, 1e-12f));
                    dbuf[c0 * 64 + p] = da;
                    dbuf[(c0 + 1) * 64 + p] = db;
                    if (cc == 0) {
                        mn[c0 * 64 + p] = da;
                        mn[(c0 + 1) * 64 + p] = db;
                    } else {
                        mn[c0 * 64 + p] = fminf(mn[c0 * 64 + p], da);
                        mn[(c0 + 1) * 64 + p] = fminf(mn[(c0 + 1) * 64 + p], db);
                    }
                }
            }
            __syncthreads();
            // Coalesced float4 writes of distances_neg for n = cc.
            const float4* d4 = (const float4*)dbuf;
            #pragma unroll
            for (int it = 0; it < 16; it++) {
                int e = it * 128 + tid;
                int c = e >> 4;
                int q = (e & 15) << 2;
                float4 v = d4[e];
                *(float4*)(out + 33554432u
                           + (size_t)((b * 128 + c) * 3 + cc) * 16384 + hw0 + q) = v;
            }
        } else {
            // Positive chunk: dist, probs, probs_ori, cls normalization.
            #pragma unroll
            for (int i = 0; i < 8; i++) {
                int p = tx * 8 + i;
                #pragma unroll
                for (int j = 0; j < 4; j++) {
                    float lo, hi; unpk(acc[i][j], lo, hi);
                    int c0 = ty * 8 + 2 * j;
                    float dots[2] = { lo, hi };
                    #pragma unroll
                    for (int h2 = 0; h2 < 2; h2++) {
                        int ci = c0 + h2;
                        float m    = fmaxf(2.f - 2.f * dots[h2], 1e-12f);
                        float dist = sqrtf(m);
                        float mv   = mn[ci * 64 + p];
                        float t    = dist + 0.3f * (2.f - mv);
                        float pr   = __expf(-2.f * t * t);
                        dbuf[ci * 64 + p] = dist;   // distances
                        mn[ci * 64 + p]   = pr;     // probs (reuse buffer)
                    }
                }
            }
            __syncthreads();
            // Per-pixel sum of probs over classes.
            {
                int p = tid & 63, h = tid >> 6;
                float s = 0.f;
                #pragma unroll 8
                for (int c = 0; c < 64; c++) s += mn[(h * 64 + c) * 64 + p];
                part[tid] = s;
            }
            __syncthreads();
            if (tid < 64) rs[tid] = 1.0f / (part[tid] + part[tid + 64]);
            __syncthreads();
            // Coalesced float4 writes: cls_score, distances, probs_ori.
            const float4* d4 = (const float4*)dbuf;
            const float4* p4 = (const float4*)mn;
            const float4* r4 = (const float4*)rs;
            #pragma unroll
            for (int it = 0; it < 16; it++) {
                int e = it * 128 + tid;
                int c = e >> 4;
                int q = (e & 15) << 2;
                float4 dv = d4[e], pv = p4[e], rv = r4[e & 15];
                float4 ev, po, cs;
                ev.x = __expf(-dv.x * dv.x); ev.y = __expf(-dv.y * dv.y);
                ev.z = __expf(-dv.z * dv.z); ev.w = __expf(-dv.w * dv.w);
                po.x = ev.x * ev.x; po.y = ev.y * ev.y;
                po.z = ev.z * ev.z; po.w = ev.w * ev.w;
                cs.x = ev.x * pv.x * rv.x; cs.y = ev.y * pv.y * rv.y;
                cs.z = ev.z * pv.z * rv.z; cs.w = ev.w * pv.w * rv.w;
                size_t base = (size_t)(b * 128 + c) * 16384 + hw0 + q;
                *(float4*)(out + base)             = cs;  // cls_score
                *(float4*)(out + 16777216u + base) = dv;  // distances
                *(float4*)(out + 83886080u + base) = po;  // probs_ori
            }
        }
    }
}

// ---------------------------------------------------------------------------
extern "C" void kernel_launch(void* const* d_in, const int* in_sizes, int n_in,
                              void* d_out, int out_size) {
    const float* x    = (const float*)d_in[0];
    const float* reps = (const float*)d_in[1];
    const float* fcw  = (const float*)d_in[2];
    const float* fcb  = (const float*)d_in[3];
    float* out = (float*)d_out;

    const int smem = 41152 * (int)sizeof(float);   // 164608 B
    cudaFuncSetAttribute(dml_main, cudaFuncAttributeMaxDynamicSharedMemorySize, smem);

    dml_prep<<<128, 128>>>(reps, fcw, fcb);
    dml_main<<<2048, 128, smem>>>(x, out);
}

// round 5
// speedup vs baseline: 1.0432x; 1.0432x over previous
#include <cuda_runtime.h>
#include <cstdint>

// Problem constants (asserted by reference):
//   x: [8, 128, 128, 128]  (B, D, H, W), HW = 16384, NPIX = 131072
//   C = 128 classes, M = 1, NEG = 3  -> 512 prototypes total
// Output tuple flattened in order:
//   cls_score  [8,128,128,128]      @ 0          (16777216)
//   distances  [8,128,1,128,128]    @ 16777216   (16777216)
//   distances_neg [8,128,3,128,128] @ 33554432   (50331648)
//   probs_ori  [8,128,128,128]      @ 83886080   (16777216)

typedef unsigned long long ull;

// Prototype matrix, pre-transposed per 128-proto chunk: g_PT[chunk*16384 + d*128 + cLocal]
// chunk 0..2 = negative prototypes n=0..2 (per class), chunk 3 = positive prototypes.
__device__ float g_PT[4 * 128 * 128];

// ---------------------------------------------------------------------------
// Prep: normalize reps, build negative prototypes, store transposed.
// grid = 128 (one CTA per class), block = 128 (one thread per channel d)
// ---------------------------------------------------------------------------
__global__ void dml_prep(const float* __restrict__ reps_w,
                         const float* __restrict__ fc_w,
                         const float* __restrict__ fc_b) {
    __shared__ float repn[128];
    __shared__ float red[128];
    const int c = blockIdx.x;
    const int d = threadIdx.x;

    float w = reps_w[c * 128 + d];
    red[d] = w * w;
    __syncthreads();
    for (int s = 64; s > 0; s >>= 1) { if (d < s) red[d] += red[d + s]; __syncthreads(); }
    float S = red[0];
    __syncthreads();
    float rn = w / fmaxf(sqrtf(S), 1e-12f);
    repn[d] = rn;
    g_PT[3 * 16384 + d * 128 + c] = rn;   // positive prototypes, chunk 3
    __syncthreads();

    for (int n = 0; n < 3; n++) {
        const float* wr = fc_w + (size_t)(n * 128 + d) * 128;
        float a = fc_b[n * 128 + d];
        #pragma unroll 8
        for (int k = 0; k < 128; k++) a += repn[k] * wr[k];
        float v = a + rn;                 // neg_off + reps_flat
        red[d] = v * v;
        __syncthreads();
        for (int s = 64; s > 0; s >>= 1) { if (d < s) red[d] += red[d + s]; __syncthreads(); }
        float S2 = red[0];
        __syncthreads();
        g_PT[n * 16384 + d * 128 + c] = v / fmaxf(sqrtf(S2), 1e-12f);
    }
}

// ---------------------------------------------------------------------------
// Packed fp32x2 helpers (Blackwell FFMA2 — only reachable via PTX)
// ---------------------------------------------------------------------------
__device__ __forceinline__ ull pk(float v) {
    ull r; asm("mov.b64 %0, {%1,%1};" : "=l"(r) : "f"(v)); return r;
}
__device__ __forceinline__ void fma2(ull& d, ull a, ull b) {
    asm("fma.rn.f32x2 %0, %1, %2, %0;" : "+l"(d) : "l"(a), "l"(b));
}
__device__ __forceinline__ void unpk(ull v, float& lo, float& hi) {
    asm("mov.b64 {%0,%1}, %2;" : "=f"(lo), "=f"(hi) : "l"(v));
}
union F4U { float4 f; ull u[2]; };

// ---------------------------------------------------------------------------
// Main fused kernel.
// grid = 2048 (8 batches * 256 pixel-tiles), block = 128 threads.
// Each CTA: 64 contiguous hw pixels of one batch image.
// Thread tile: 8 px * 8 protos (protos packed pairwise for f32x2).
// smem: xs[128k][64px] | pt[128k][128proto] | dbuf[128c][64px] | mn[128c][64px]
//       | rs[64] | part[128]   (total 41152 floats = 164608 B)
// ---------------------------------------------------------------------------
__global__ __launch_bounds__(128, 1)
void dml_main(const float* __restrict__ x, float* __restrict__ out) {
    extern __shared__ float sm[];
    float* xs   = sm;            // 8192
    float* pt   = sm + 8192;     // 16384
    float* dbuf = sm + 24576;    // 8192
    float* mn   = sm + 32768;    // 8192
    float* rs   = sm + 40960;    // 64
    float* part = sm + 41024;    // 128

    const int tid = threadIdx.x;
    const int b   = blockIdx.x >> 8;
    const int hw0 = (blockIdx.x & 255) << 6;
    const float* xb = x + ((size_t)b * 128) * 16384 + hw0;

    // Load x tile: xs[d][px] — contiguous px dimension, coalesced.
    for (int i = tid; i < 8192; i += 128)
        xs[i] = xb[(size_t)(i >> 6) * 16384 + (i & 63)];
    __syncthreads();

    // Per-pixel L2 norm, fold into xs (emb = x / max(||x||, eps)).
    {
        int p = tid & 63, h = tid >> 6;
        float s = 0.f;
        #pragma unroll 8
        for (int d = 0; d < 64; d++) { float v = xs[(h * 64 + d) * 64 + p]; s += v * v; }
        part[tid] = s;
    }
    __syncthreads();
    if (tid < 64) rs[tid] = 1.0f / fmaxf(sqrtf(part[tid] + part[tid + 64]), 1e-12f);
    __syncthreads();
    for (int i = tid; i < 8192; i += 128) xs[i] *= rs[i & 63];

    const int tx = tid & 7;    // pixel-group  (8 px each)
    const int ty = tid >> 3;   // proto-group  (8 protos each)
    const float4* xs4 = (const float4*)xs;
    const float4* pt4 = (const float4*)pt;

    for (int cc = 0; cc < 4; cc++) {
        __syncthreads();   // protect pt + dbuf reuse
        {
            const float4* gp = (const float4*)(g_PT + cc * 16384);
            float4* w4 = (float4*)pt;
            for (int i = tid; i < 4096; i += 128) w4[i] = gp[i];
        }
        __syncthreads();

        ull acc[8][4];
        #pragma unroll
        for (int i = 0; i < 8; i++)
            #pragma unroll
            for (int j = 0; j < 4; j++) acc[i][j] = 0ULL;

        #pragma unroll 4
        for (int k = 0; k < 128; k++) {
            float4 xa = xs4[k * 16 + tx * 2];
            float4 xc = xs4[k * 16 + tx * 2 + 1];
            F4U p0, p1;
            p0.f = pt4[k * 32 + ty * 2];
            p1.f = pt4[k * 32 + ty * 2 + 1];
            ull xq[8] = { pk(xa.x), pk(xa.y), pk(xa.z), pk(xa.w),
                          pk(xc.x), pk(xc.y), pk(xc.z), pk(xc.w) };
            #pragma unroll
            for (int i = 0; i < 8; i++) {
                fma2(acc[i][0], p0.u[0], xq[i]);
                fma2(acc[i][1], p0.u[1], xq[i]);
                fma2(acc[i][2], p1.u[0], xq[i]);
                fma2(acc[i][3], p1.u[1], xq[i]);
            }
        }

        if (cc < 3) {
            // Negative chunk: distances_neg + running min.
            #pragma unroll
            for (int i = 0; i < 8; i++) {
                int p = tx * 8 + i;
                #pragma unroll
                for (int j = 0; j < 4; j++) {
                    float lo, hi; unpk(acc[i][j], lo, hi);
                    int c0 = ty * 8 + 2 * j;
                    float da = sqrtf(fmaxf(2.f - 2.f * lo, 1e-12f));
                    float db = sqrtf(fmaxf(2.f - 2.f * hi, 1e-12f));
                    dbuf[c0 * 64 + p] = da;
                    dbuf[(c0 + 1) * 64 + p] = db;
                    if (cc == 0) {
                        mn[c0 * 64 + p] = da;
                        mn[(c0 + 1) * 64 + p] = db;
                    } else {
                        mn[c0 * 64 + p] = fminf(mn[c0 * 64 + p], da);
                        mn[(c0 + 1) * 64 + p] = fminf(mn[(c0 + 1) * 64 + p], db);
                    }
                }
            }
            __syncthreads();
            // Coalesced float4 writes of distances_neg for n = cc.
            const float4* d4 = (const float4*)dbuf;
            #pragma unroll
            for (int it = 0; it < 16; it++) {
                int e = it * 128 + tid;
                int c = e >> 4;
                int q = (e & 15) << 2;
                float4 v = d4[e];
                *(float4*)(out + 33554432u
                           + (size_t)((b * 128 + c) * 3 + cc) * 16384 + hw0 + q) = v;
            }
        } else {
            // Positive chunk: dist, probs, probs_ori, cls normalization.
            #pragma unroll
            for (int i = 0; i < 8; i++) {
                int p = tx * 8 + i;
                #pragma unroll
                for (int j = 0; j < 4; j++) {
                    float lo, hi; unpk(acc[i][j], lo, hi);
                    int c0 = ty * 8 + 2 * j;
                    float dots[2] = { lo, hi };
                    #pragma unroll
                    for (int h2 = 0; h2 < 2; h2++) {
                        int ci = c0 + h2;
                        float m    = fmaxf(2.f - 2.f * dots[h2], 1e-12f);
                        float dist = sqrtf(m);
                        float mv   = mn[ci * 64 + p];
                        float t    = dist + 0.3f * (2.f - mv);
                        float pr   = __expf(-2.f * t * t);
                        dbuf[ci * 64 + p] = dist;   // distances
                        mn[ci * 64 + p]   = pr;     // probs (reuse buffer)
                    }
                }
            }
            __syncthreads();
            // Per-pixel sum of probs over classes.
            {
                int p = tid & 63, h = tid >> 6;
                float s = 0.f;
                #pragma unroll 8
                for (int c = 0; c < 64; c++) s += mn[(h * 64 + c) * 64 + p];
                part[tid] = s;
            }
            __syncthreads();
            if (tid < 64) rs[tid] = 1.0f / (part[tid] + part[tid + 64]);
            __syncthreads();
            // Coalesced float4 writes: cls_score, distances, probs_ori.
            const float4* d4 = (const float4*)dbuf;
            const float4* p4 = (const float4*)mn;
            const float4* r4 = (const float4*)rs;
            #pragma unroll
            for (int it = 0; it < 16; it++) {
                int e = it * 128 + tid;
                int c = e >> 4;
                int q = (e & 15) << 2;
                float4 dv = d4[e], pv = p4[e], rv = r4[e & 15];
                float4 ev, po, cs;
                ev.x = __expf(-dv.x * dv.x); ev.y = __expf(-dv.y * dv.y);
                ev.z = __expf(-dv.z * dv.z); ev.w = __expf(-dv.w * dv.w);
                po.x = ev.x * ev.x; po.y = ev.y * ev.y;
                po.z = ev.z * ev.z; po.w = ev.w * ev.w;
                cs.x = ev.x * pv.x * rv.x; cs.y = ev.y * pv.y * rv.y;
                cs.z = ev.z * pv.z * rv.z; cs.w = ev.w * pv.w * rv.w;
                size_t base = (size_t)(b * 128 + c) * 16384 + hw0 + q;
                *(float4*)(out + base)             = cs;  // cls_score
                *(float4*)(out + 16777216u + base) = dv;  // distances
                *(float4*)(out + 83886080u + base) = po;  // probs_ori
            }
        }
    }
}

// ---------------------------------------------------------------------------
extern "C" void kernel_launch(void* const* d_in, const int* in_sizes, int n_in,
                              void* d_out, int out_size) {
    const float* x    = (const float*)d_in[0];
    const float* reps = (const float*)d_in[1];
    const float* fcw  = (const float*)d_in[2];
    const float* fcb  = (const float*)d_in[3];
    float* out = (float*)d_out;

    const int smem = 41152 * (int)sizeof(float);   // 164608 B
    cudaFuncSetAttribute(dml_main, cudaFuncAttributeMaxDynamicSharedMemorySize, smem);

    dml_prep<<<128, 128>>>(reps, fcw, fcb);
    dml_main<<<2048, 128, smem>>>(x, out);
}

// round 6
// speedup vs baseline: 1.4615x; 1.4009x over previous
#include <cuda_runtime.h>
#include <cstdint>

// Problem constants:
//   x: [8, 128, 128, 128]  (B, D, H, W), HW = 16384, NPIX = 131072
//   C = 128 classes, M = 1, NEG = 3  -> 512 prototypes total
// Output tuple flattened:
//   cls_score  @ 0          (16777216)
//   distances  @ 16777216   (16777216)
//   distances_neg @ 33554432 (50331648)
//   probs_ori  @ 83886080   (16777216)

typedef unsigned long long ull;

// Prototype matrix, pre-transposed per 128-proto chunk: g_PT[chunk*16384 + d*128 + cLocal]
__device__ float g_PT[4 * 128 * 128];

// ---------------------------------------------------------------------------
// Prep: normalize reps, build negative prototypes, store transposed.
// ---------------------------------------------------------------------------
__global__ void dml_prep(const float* __restrict__ reps_w,
                         const float* __restrict__ fc_w,
                         const float* __restrict__ fc_b) {
    __shared__ float repn[128];
    __shared__ float red[128];
    const int c = blockIdx.x;
    const int d = threadIdx.x;

    float w = reps_w[c * 128 + d];
    red[d] = w * w;
    __syncthreads();
    for (int s = 64; s > 0; s >>= 1) { if (d < s) red[d] += red[d + s]; __syncthreads(); }
    float S = red[0];
    __syncthreads();
    float rn = w / fmaxf(sqrtf(S), 1e-12f);
    repn[d] = rn;
    g_PT[3 * 16384 + d * 128 + c] = rn;
    __syncthreads();

    for (int n = 0; n < 3; n++) {
        const float* wr = fc_w + (size_t)(n * 128 + d) * 128;
        float a = fc_b[n * 128 + d];
        #pragma unroll 8
        for (int k = 0; k < 128; k++) a += repn[k] * wr[k];
        float v = a + rn;
        red[d] = v * v;
        __syncthreads();
        for (int s = 64; s > 0; s >>= 1) { if (d < s) red[d] += red[d + s]; __syncthreads(); }
        float S2 = red[0];
        __syncthreads();
        g_PT[n * 16384 + d * 128 + c] = v / fmaxf(sqrtf(S2), 1e-12f);
    }
}

// ---------------------------------------------------------------------------
// Packed fp32x2 helpers (Blackwell FFMA2)
// ---------------------------------------------------------------------------
__device__ __forceinline__ ull pk(float v) {
    ull r; asm("mov.b64 %0, {%1,%1};" : "=l"(r) : "f"(v)); return r;
}
__device__ __forceinline__ void fma2(ull& d, ull a, ull b) {
    asm("fma.rn.f32x2 %0, %1, %2, %0;" : "+l"(d) : "l"(a), "l"(b));
}
__device__ __forceinline__ void unpk(ull v, float& lo, float& hi) {
    asm("mov.b64 {%0,%1}, %2;" : "=f"(lo), "=f"(hi) : "l"(v));
}
union F4U { float4 f; ull u[2]; };

// ---------------------------------------------------------------------------
// Main fused kernel.
// grid = 2048 (8 batches * 256 pixel-tiles), block = 256 threads (8 warps).
// Each CTA: 64 contiguous hw pixels. Thread tile: 4 px * 8 protos.
// smem: xs[128k][64px] | pt[128k][128proto] | dbuf[128c][64px] | mn[128c][64px]
//       | rs[64] | part[256]   (41280 floats = 165120 B) -> 1 CTA/SM, 8 warps.
// ---------------------------------------------------------------------------
__global__ __launch_bounds__(256, 1)
void dml_main(const float* __restrict__ x, float* __restrict__ out) {
    extern __shared__ float sm[];
    float* xs   = sm;            // 8192
    float* pt   = sm + 8192;     // 16384
    float* dbuf = sm + 24576;    // 8192
    float* mn   = sm + 32768;    // 8192
    float* rs   = sm + 40960;    // 64
    float* part = sm + 41024;    // 256

    const int tid = threadIdx.x;
    const int b   = blockIdx.x >> 8;
    const int hw0 = (blockIdx.x & 255) << 6;
    const float* xb = x + ((size_t)b * 128) * 16384 + hw0;

    // Load x tile: xs[d][px]  (coalesced over px)
    for (int i = tid; i < 8192; i += 256)
        xs[i] = xb[(size_t)(i >> 6) * 16384 + (i & 63)];
    __syncthreads();

    // Per-pixel L2 norm, fold into xs.
    {
        int p = tid & 63, h = tid >> 6;            // 4 channel-groups of 32
        float s = 0.f;
        #pragma unroll 8
        for (int d = 0; d < 32; d++) { float v = xs[(h * 32 + d) * 64 + p]; s += v * v; }
        part[tid] = s;
    }
    __syncthreads();
    if (tid < 64)
        rs[tid] = 1.0f / fmaxf(sqrtf(part[tid] + part[tid + 64] +
                                     part[tid + 128] + part[tid + 192]), 1e-12f);
    __syncthreads();
    for (int i = tid; i < 8192; i += 256) xs[i] *= rs[i & 63];

    const int tx = tid & 15;   // pixel-group  (4 px each, 16 groups)
    const int ty = tid >> 4;   // proto-group  (8 protos each, 16 groups)
    const float4* xs4 = (const float4*)xs;
    const float4* pt4 = (const float4*)pt;

    for (int cc = 0; cc < 4; cc++) {
        __syncthreads();   // protect pt + dbuf reuse
        {
            const float4* gp = (const float4*)(g_PT + cc * 16384);
            float4* w4 = (float4*)pt;
            for (int i = tid; i < 4096; i += 256) w4[i] = gp[i];
        }
        __syncthreads();

        ull acc[4][4];
        #pragma unroll
        for (int i = 0; i < 4; i++)
            #pragma unroll
            for (int j = 0; j < 4; j++) acc[i][j] = 0ULL;

        #pragma unroll 4
        for (int k = 0; k < 128; k++) {
            float4 xa = xs4[k * 16 + tx];
            F4U p0, p1;
            p0.f = pt4[k * 32 + ty * 2];
            p1.f = pt4[k * 32 + ty * 2 + 1];
            ull xq[4] = { pk(xa.x), pk(xa.y), pk(xa.z), pk(xa.w) };
            #pragma unroll
            for (int i = 0; i < 4; i++) {
                fma2(acc[i][0], p0.u[0], xq[i]);
                fma2(acc[i][1], p0.u[1], xq[i]);
                fma2(acc[i][2], p1.u[0], xq[i]);
                fma2(acc[i][3], p1.u[1], xq[i]);
            }
        }

        if (cc < 3) {
            // Negative chunk: distances_neg + running min.
            #pragma unroll
            for (int i = 0; i < 4; i++) {
                int p = tx * 4 + i;
                #pragma unroll
                for (int j = 0; j < 4; j++) {
                    float lo, hi; unpk(acc[i][j], lo, hi);
                    int c0 = ty * 8 + 2 * j;
                    float da = sqrtf(fmaxf(2.f - 2.f * lo, 1e-12f));
                    float db = sqrtf(fmaxf(2.f - 2.f * hi, 1e-12f));
                    dbuf[c0 * 64 + p] = da;
                    dbuf[(c0 + 1) * 64 + p] = db;
                    if (cc == 0) {
                        mn[c0 * 64 + p] = da;
                        mn[(c0 + 1) * 64 + p] = db;
                    } else {
                        mn[c0 * 64 + p] = fminf(mn[c0 * 64 + p], da);
                        mn[(c0 + 1) * 64 + p] = fminf(mn[(c0 + 1) * 64 + p], db);
                    }
                }
            }
            __syncthreads();
            const float4* d4 = (const float4*)dbuf;
            #pragma unroll
            for (int it = 0; it < 8; it++) {
                int e = it * 256 + tid;
                int c = e >> 4;
                int q = (e & 15) << 2;
                float4 v = d4[e];
                *(float4*)(out + 33554432u
                           + (size_t)((b * 128 + c) * 3 + cc) * 16384 + hw0 + q) = v;
            }
        } else {
            // Positive chunk: dist, probs, probs_ori, cls normalization.
            #pragma unroll
            for (int i = 0; i < 4; i++) {
                int p = tx * 4 + i;
                #pragma unroll
                for (int j = 0; j < 4; j++) {
                    float lo, hi; unpk(acc[i][j], lo, hi);
                    int c0 = ty * 8 + 2 * j;
                    float dots[2] = { lo, hi };
                    #pragma unroll
                    for (int h2 = 0; h2 < 2; h2++) {
                        int ci = c0 + h2;
                        float m    = fmaxf(2.f - 2.f * dots[h2], 1e-12f);
                        float dist = sqrtf(m);
                        float mv   = mn[ci * 64 + p];
                        float t    = dist + 0.3f * (2.f - mv);
                        float pr   = __expf(-2.f * t * t);
                        dbuf[ci * 64 + p] = dist;   // distances
                        mn[ci * 64 + p]   = pr;     // probs (reuse buffer)
                    }
                }
            }
            __syncthreads();
            // Per-pixel sum of probs over classes.
            {
                int p = tid & 63, h = tid >> 6;
                float s = 0.f;
                #pragma unroll 8
                for (int c = 0; c < 32; c++) s += mn[(h * 32 + c) * 64 + p];
                part[tid] = s;
            }
            __syncthreads();
            if (tid < 64)
                rs[tid] = 1.0f / (part[tid] + part[tid + 64] +
                                  part[tid + 128] + part[tid + 192]);
            __syncthreads();
            const float4* d4 = (const float4*)dbuf;
            const float4* p4 = (const float4*)mn;
            const float4* r4 = (const float4*)rs;
            #pragma unroll
            for (int it = 0; it < 8; it++) {
                int e = it * 256 + tid;
                int c = e >> 4;
                int q = (e & 15) << 2;
                float4 dv = d4[e], pv = p4[e], rv = r4[e & 15];
                float4 ev, po, cs;
                ev.x = __expf(-dv.x * dv.x); ev.y = __expf(-dv.y * dv.y);
                ev.z = __expf(-dv.z * dv.z); ev.w = __expf(-dv.w * dv.w);
                po.x = ev.x * ev.x; po.y = ev.y * ev.y;
                po.z = ev.z * ev.z; po.w = ev.w * ev.w;
                cs.x = ev.x * pv.x * rv.x; cs.y = ev.y * pv.y * rv.y;
                cs.z = ev.z * pv.z * rv.z; cs.w = ev.w * pv.w * rv.w;
                size_t base = (size_t)(b * 128 + c) * 16384 + hw0 + q;
                *(float4*)(out + base)             = cs;  // cls_score
                *(float4*)(out + 16777216u + base) = dv;  // distances
                *(float4*)(out + 83886080u + base) = po;  // probs_ori
            }
        }
    }
}

// ---------------------------------------------------------------------------
extern "C" void kernel_launch(void* const* d_in, const int* in_sizes, int n_in,
                              void* d_out, int out_size) {
    const float* x    = (const float*)d_in[0];
    const float* reps = (const float*)d_in[1];
    const float* fcw  = (const float*)d_in[2];
    const float* fcb  = (const float*)d_in[3];
    float* out = (float*)d_out;

    const int smem = 41280 * (int)sizeof(float);   // 165120 B
    cudaFuncSetAttribute(dml_main, cudaFuncAttributeMaxDynamicSharedMemorySize, smem);

    dml_prep<<<128, 128>>>(reps, fcw, fcb);
    dml_main<<<2048, 256, smem>>>(x, out);
}

// round 7
// speedup vs baseline: 1.8994x; 1.2996x over previous
#include <cuda_runtime.h>
#include <cstdint>

// Problem constants:
//   x: [8, 128, 128, 128]  (B, D, H, W), HW = 16384, NPIX = 131072
//   C = 128 classes, M = 1, NEG = 3  -> 512 prototypes total
// Output tuple flattened:
//   cls_score     @ 0         (16777216)
//   distances     @ 16777216  (16777216)
//   distances_neg @ 33554432  (50331648)
//   probs_ori     @ 83886080  (16777216)

typedef unsigned long long ull;

// Prototypes, pre-transposed per 128-proto chunk: g_PT[chunk*16384 + d*128 + cLocal]
// chunks 0..2 = negative prototypes n=0..2, chunk 3 = positive prototypes.
__device__ float g_PT[4 * 128 * 128];

// ---------------------------------------------------------------------------
// Prep: normalize reps, build negative prototypes, store transposed.
// ---------------------------------------------------------------------------
__global__ void dml_prep(const float* __restrict__ reps_w,
                         const float* __restrict__ fc_w,
                         const float* __restrict__ fc_b) {
    __shared__ float repn[128];
    __shared__ float red[128];
    const int c = blockIdx.x;
    const int d = threadIdx.x;

    float w = reps_w[c * 128 + d];
    red[d] = w * w;
    __syncthreads();
    for (int s = 64; s > 0; s >>= 1) { if (d < s) red[d] += red[d + s]; __syncthreads(); }
    float S = red[0];
    __syncthreads();
    float rn = w / fmaxf(sqrtf(S), 1e-12f);
    repn[d] = rn;
    g_PT[3 * 16384 + d * 128 + c] = rn;
    __syncthreads();

    for (int n = 0; n < 3; n++) {
        const float* wr = fc_w + (size_t)(n * 128 + d) * 128;
        float a = fc_b[n * 128 + d];
        #pragma unroll 8
        for (int k = 0; k < 128; k++) a += repn[k] * wr[k];
        float v = a + rn;
        red[d] = v * v;
        __syncthreads();
        for (int s = 64; s > 0; s >>= 1) { if (d < s) red[d] += red[d + s]; __syncthreads(); }
        float S2 = red[0];
        __syncthreads();
        g_PT[n * 16384 + d * 128 + c] = v / fmaxf(sqrtf(S2), 1e-12f);
    }
}

// ---------------------------------------------------------------------------
// Packed fp32x2 helpers (Blackwell FFMA2)
// ---------------------------------------------------------------------------
__device__ __forceinline__ ull pk(float v) {
    ull r; asm("mov.b64 %0, {%1,%1};" : "=l"(r) : "f"(v)); return r;
}
__device__ __forceinline__ void fma2(ull& d, ull a, ull b) {
    asm("fma.rn.f32x2 %0, %1, %2, %0;" : "+l"(d) : "l"(a), "l"(b));
}
__device__ __forceinline__ void unpk(ull v, float& lo, float& hi) {
    asm("mov.b64 {%0,%1}, %2;" : "=f"(lo), "=f"(hi) : "l"(v));
}
union F4U { float4 f; ull u[2]; };

// ---------------------------------------------------------------------------
// Main fused kernel.
// grid = 2048, block = 256 (8 warps), 2 CTAs/SM (16 warps/SM).
// Each CTA: 64 contiguous hw pixels. Thread tile: 4 px * 8 protos.
// Epilogue is register-resident: min-over-negs is thread-local; all gmem
// stores are direct from registers (256B-coalesced per half-warp).
// smem: xs[128k][64px] (8192) | pt[128k][128proto] (16384) | red (1024)
//       | rs (64)  = 25664 floats = 102656 B  -> fits 2 CTAs/SM.
// ---------------------------------------------------------------------------
__global__ __launch_bounds__(256, 2)
void dml_main(const float* __restrict__ x, float* __restrict__ out) {
    extern __shared__ float sm[];
    float* xs  = sm;            // 8192
    float* pt  = sm + 8192;     // 16384
    float* red = sm + 24576;    // 1024 (also norm partials)
    float* rs  = sm + 25600;    // 64

    const int tid = threadIdx.x;
    const int b   = blockIdx.x >> 8;
    const int hw0 = (blockIdx.x & 255) << 6;
    const float* xb = x + ((size_t)b * 128) * 16384 + hw0;

    // Load x tile: xs[d][px]  (coalesced over px)
    for (int i = tid; i < 8192; i += 256)
        xs[i] = xb[(size_t)(i >> 6) * 16384 + (i & 63)];
    __syncthreads();

    // Per-pixel L2 norm, fold into xs.
    {
        int p = tid & 63, h = tid >> 6;      // 4 channel-groups of 32
        float s = 0.f;
        #pragma unroll 8
        for (int d = 0; d < 32; d++) { float v = xs[(h * 32 + d) * 64 + p]; s += v * v; }
        red[tid] = s;
    }
    __syncthreads();
    if (tid < 64)
        rs[tid] = 1.0f / fmaxf(sqrtf(red[tid] + red[tid + 64] +
                                     red[tid + 128] + red[tid + 192]), 1e-12f);
    __syncthreads();
    for (int i = tid; i < 8192; i += 256) xs[i] *= rs[i & 63];

    const int tx = tid & 15;   // pixel-group  (4 px each)
    const int ty = tid >> 4;   // proto-group  (8 protos each)
    const float4* xs4 = (const float4*)xs;
    const float4* pt4 = (const float4*)pt;

    float mnreg[4][8];         // thread-local min over negs [px][class]

    for (int cc = 0; cc < 4; cc++) {
        __syncthreads();       // pt reuse
        {
            const float4* gp = (const float4*)(g_PT + cc * 16384);
            float4* w4 = (float4*)pt;
            for (int i = tid; i < 4096; i += 256) w4[i] = gp[i];
        }
        __syncthreads();

        ull acc[4][4];
        #pragma unroll
        for (int i = 0; i < 4; i++)
            #pragma unroll
            for (int j = 0; j < 4; j++) acc[i][j] = 0ULL;

        #pragma unroll 4
        for (int k = 0; k < 128; k++) {
            float4 xa = xs4[k * 16 + tx];
            F4U p0, p1;
            p0.f = pt4[k * 32 + ty * 2];
            p1.f = pt4[k * 32 + ty * 2 + 1];
            ull xq[4] = { pk(xa.x), pk(xa.y), pk(xa.z), pk(xa.w) };
            #pragma unroll
            for (int i = 0; i < 4; i++) {
                fma2(acc[i][0], p0.u[0], xq[i]);
                fma2(acc[i][1], p0.u[1], xq[i]);
                fma2(acc[i][2], p1.u[0], xq[i]);
                fma2(acc[i][3], p1.u[1], xq[i]);
            }
        }

        if (cc < 3) {
            // Negative chunk: distances_neg straight to gmem, min in regs.
            #pragma unroll
            for (int j = 0; j < 4; j++) {
                float lo[4], hi[4];
                #pragma unroll
                for (int i = 0; i < 4; i++) unpk(acc[i][j], lo[i], hi[i]);
                float4 dl, dh;
                dl.x = sqrtf(fmaxf(2.f - 2.f * lo[0], 1e-12f));
                dl.y = sqrtf(fmaxf(2.f - 2.f * lo[1], 1e-12f));
                dl.z = sqrtf(fmaxf(2.f - 2.f * lo[2], 1e-12f));
                dl.w = sqrtf(fmaxf(2.f - 2.f * lo[3], 1e-12f));
                dh.x = sqrtf(fmaxf(2.f - 2.f * hi[0], 1e-12f));
                dh.y = sqrtf(fmaxf(2.f - 2.f * hi[1], 1e-12f));
                dh.z = sqrtf(fmaxf(2.f - 2.f * hi[2], 1e-12f));
                dh.w = sqrtf(fmaxf(2.f - 2.f * hi[3], 1e-12f));
                int c0 = ty * 8 + 2 * j;
                if (cc == 0) {
                    mnreg[0][2*j] = dl.x; mnreg[1][2*j] = dl.y;
                    mnreg[2][2*j] = dl.z; mnreg[3][2*j] = dl.w;
                    mnreg[0][2*j+1] = dh.x; mnreg[1][2*j+1] = dh.y;
                    mnreg[2][2*j+1] = dh.z; mnreg[3][2*j+1] = dh.w;
                } else {
                    mnreg[0][2*j] = fminf(mnreg[0][2*j], dl.x);
                    mnreg[1][2*j] = fminf(mnreg[1][2*j], dl.y);
                    mnreg[2][2*j] = fminf(mnreg[2][2*j], dl.z);
                    mnreg[3][2*j] = fminf(mnreg[3][2*j], dl.w);
                    mnreg[0][2*j+1] = fminf(mnreg[0][2*j+1], dh.x);
                    mnreg[1][2*j+1] = fminf(mnreg[1][2*j+1], dh.y);
                    mnreg[2][2*j+1] = fminf(mnreg[2][2*j+1], dh.z);
                    mnreg[3][2*j+1] = fminf(mnreg[3][2*j+1], dh.w);
                }
                size_t b0 = 33554432u
                          + (size_t)((b * 128 + c0) * 3 + cc) * 16384 + hw0 + tx * 4;
                *(float4*)(out + b0)             = dl;
                *(float4*)(out + b0 + 3 * 16384) = dh;   // class c0+1
            }
        } else {
            // Positive chunk: distances, probs_ori direct; q=ev*pr held for
            // cls_score after the class-sum reduction.
            float q[4][8];
            float psum[4] = {0.f, 0.f, 0.f, 0.f};
            #pragma unroll
            for (int j = 0; j < 4; j++) {
                float lo[4], hi[4];
                #pragma unroll
                for (int i = 0; i < 4; i++) unpk(acc[i][j], lo[i], hi[i]);
                int c0 = ty * 8 + 2 * j;
                float4 dl, po_l, dh, po_h;
                #pragma unroll
                for (int h2 = 0; h2 < 2; h2++) {
                    float* dot = h2 ? hi : lo;
                    float4 dv, po;
                    float* dvp = &dv.x; float* pop = &po.x;
                    #pragma unroll
                    for (int i = 0; i < 4; i++) {
                        float dist = sqrtf(fmaxf(2.f - 2.f * dot[i], 1e-12f));
                        float ev   = __expf(-dist * dist);
                        float t    = dist + 0.3f * (2.f - mnreg[i][2*j + h2]);
                        float pr   = __expf(-2.f * t * t);
                        dvp[i] = dist;
                        pop[i] = ev * ev;
                        q[i][2*j + h2] = ev * pr;
                        psum[i] += pr;
                    }
                    size_t base = (size_t)(b * 128 + c0 + h2) * 16384 + hw0 + tx * 4;
                    *(float4*)(out + 16777216u + base) = dv;  // distances
                    *(float4*)(out + 83886080u + base) = po;  // probs_ori
                }
            }
            // Per-pixel class-sum across the 16 ty groups.
            #pragma unroll
            for (int i = 0; i < 4; i++) red[ty * 64 + tx * 4 + i] = psum[i];
            __syncthreads();
            if (tid < 64) {
                float s = 0.f;
                #pragma unroll
                for (int t = 0; t < 16; t++) s += red[t * 64 + tid];
                rs[tid] = 1.0f / s;
            }
            __syncthreads();
            float4 rv = ((const float4*)rs)[tx];
            const float* rvp = &rv.x;
            #pragma unroll
            for (int j = 0; j < 8; j++) {
                float4 cs;
                cs.x = q[0][j] * rvp[0];
                cs.y = q[1][j] * rvp[1];
                cs.z = q[2][j] * rvp[2];
                cs.w = q[3][j] * rvp[3];
                size_t base = (size_t)(b * 128 + ty * 8 + j) * 16384 + hw0 + tx * 4;
                *(float4*)(out + base) = cs;  // cls_score
            }
        }
    }
}

// ---------------------------------------------------------------------------
extern "C" void kernel_launch(void* const* d_in, const int* in_sizes, int n_in,
                              void* d_out, int out_size) {
    const float* x    = (const float*)d_in[0];
    const float* reps = (const float*)d_in[1];
    const float* fcw  = (const float*)d_in[2];
    const float* fcb  = (const float*)d_in[3];
    float* out = (float*)d_out;

    const int smem = 25664 * (int)sizeof(float);   // 102656 B
    cudaFuncSetAttribute(dml_main, cudaFuncAttributeMaxDynamicSharedMemorySize, smem);

    dml_prep<<<128, 128>>>(reps, fcw, fcb);
    dml_main<<<2048, 256, smem>>>(x, out);
}

// round 9
// speedup vs baseline: 3.2199x; 1.6953x over previous
#include <cuda_runtime.h>
#include <cstdint>

// Problem constants:
//   x: [8, 128, 128, 128]  (B, D, H, W), HW = 16384, NPIX = 131072
//   C = 128, M = 1, NEG = 3  -> 512 prototypes total
// Output tuple flattened:
//   cls_score     @ 0         (16777216)
//   distances     @ 16777216  (16777216)
//   distances_neg @ 33554432  (50331648)
//   probs_ori     @ 83886080  (16777216)

typedef unsigned long long ull;

// Prototypes as tf32 bits, sigma-permuted within each row:
// g_PT[chunk*16384 + class*128 + sigma(k)], chunks 0..2 = negs, 3 = positives.
__device__ __align__(16) uint32_t g_PT[4 * 128 * 128];

// k-permutation within each 8-block: pos = 2*(k&3) + ((k>>2)&1)
// => (c, c+4) fragment pairs are adjacent -> single LDS.64 per fragment.
__device__ __forceinline__ int sigma(int k) {
    return (k >> 3) * 8 + 2 * (k & 3) + ((k >> 2) & 1);
}

__device__ __forceinline__ uint32_t to_tf32(float f) {
    uint32_t u; asm("cvt.rna.tf32.f32 %0, %1;" : "=r"(u) : "f"(f)); return u;
}

__device__ __forceinline__ uint32_t smem_u32(const void* p) {
    uint32_t a;
    asm("{ .reg .u64 t; cvta.to.shared.u64 t, %1; cvt.u32.u64 %0, t; }" : "=r"(a) : "l"(p));
    return a;
}

__device__ __forceinline__ void cpa16(uint32_t dst, const void* src) {
    asm volatile("cp.async.ca.shared.global [%0], [%1], 16;" :: "r"(dst), "l"(src) : "memory");
}
#define CP_COMMIT() asm volatile("cp.async.commit_group;" ::: "memory")
#define CP_WAIT(n)  asm volatile("cp.async.wait_group %0;" :: "n"(n) : "memory")

// tf32 mma m16n8k8 (sm_80+, valid at base sm_103 target).
__device__ __forceinline__ void mma8(float* d, uint2 a01, uint2 a23, uint2 bv) {
    asm volatile(
        "mma.sync.aligned.m16n8k8.row.col.f32.tf32.tf32.f32 "
        "{%0,%1,%2,%3}, {%4,%5,%6,%7}, {%8,%9}, {%0,%1,%2,%3};"
        : "+f"(d[0]), "+f"(d[1]), "+f"(d[2]), "+f"(d[3])
        : "r"(a01.x), "r"(a23.x), "r"(a01.y), "r"(a23.y), "r"(bv.x), "r"(bv.y));
}

// ---------------------------------------------------------------------------
// Prep: normalize reps, build negatives, store tf32 sigma-permuted.
// ---------------------------------------------------------------------------
__global__ void dml_prep(const float* __restrict__ reps_w,
                         const float* __restrict__ fc_w,
                         const float* __restrict__ fc_b) {
    __shared__ float repn[128];
    __shared__ float red[128];
    const int c = blockIdx.x;
    const int d = threadIdx.x;

    float w = reps_w[c * 128 + d];
    red[d] = w * w;
    __syncthreads();
    for (int s = 64; s > 0; s >>= 1) { if (d < s) red[d] += red[d + s]; __syncthreads(); }
    float S = red[0];
    __syncthreads();
    float rn = w / fmaxf(sqrtf(S), 1e-12f);
    repn[d] = rn;
    g_PT[3 * 16384 + c * 128 + sigma(d)] = to_tf32(rn);
    __syncthreads();

    for (int n = 0; n < 3; n++) {
        const float* wr = fc_w + (size_t)(n * 128 + d) * 128;
        float a = fc_b[n * 128 + d];
        #pragma unroll 8
        for (int k = 0; k < 128; k++) a += repn[k] * wr[k];
        float v = a + rn;
        red[d] = v * v;
        __syncthreads();
        for (int s = 64; s > 0; s >>= 1) { if (d < s) red[d] += red[d + s]; __syncthreads(); }
        float S2 = red[0];
        __syncthreads();
        g_PT[n * 16384 + c * 128 + sigma(d)] = to_tf32(v / fmaxf(sqrtf(S2), 1e-12f));
    }
}

// ---------------------------------------------------------------------------
// Main: tf32 mma.sync GEMM [128px x 128k] x [128k x 512proto] + fused epilogue.
// grid = 1024, block = 256 (8 warps), 1 CTA/SM.
// Warp tile per chunk: 16 classes x 128 px (16 n-tiles of m16n8k8).
// smem (floats, stride 136 rows):
//   xs  [0, 17408)        x in tf32, [px][sigma(k)]
//   pt0 [17408, 34816)    proto chunk buffer 0 (also raw-x staging)
//   pt1 [34816, 52224)    proto chunk buffer 1
//   red [52224, 52480) | rs [52480, 52608) | psm [52608, 53632)
// total 53632 floats = 214528 B.
// ---------------------------------------------------------------------------
#define STRIDE 136

__global__ __launch_bounds__(256, 1)
void dml_main(const float* __restrict__ x, float* __restrict__ out) {
    extern __shared__ float sm[];
    uint32_t* xs  = (uint32_t*)sm;
    float*    stg = sm + 17408;                      // raw x staging (pt0 alias)
    const uint32_t* pt[2] = { (const uint32_t*)(sm + 17408),
                              (const uint32_t*)(sm + 34816) };
    float* red = sm + 52224;
    float* rs  = sm + 52480;
    float* psm = sm + 52608;
    const uint32_t sbase = smem_u32(sm);
    const uint32_t ptb[2] = { sbase + 17408u * 4u, sbase + 34816u * 4u };

    const int tid  = threadIdx.x;
    const int wid  = tid >> 5;
    const int lane = tid & 31;
    const int gq   = lane >> 2;     // group id (class row / B n-index)
    const int jj   = lane & 3;      // thread-in-group (k index / C px pair)
    const int b    = blockIdx.x >> 7;
    const int hw0  = (blockIdx.x & 127) << 7;

    // ---- Stage raw x [128k][128px] (coalesced float4) ----
    {
        const float4* xb4 = (const float4*)(x + ((size_t)b * 128) * 16384 + hw0);
        float4* st4 = (float4*)stg;
        #pragma unroll
        for (int it = 0; it < 16; it++) {
            int i = it * 256 + tid;
            st4[i] = xb4[(i >> 5) * 4096 + (i & 31)];
        }
    }
    __syncthreads();

    // ---- Transpose to xs[px][sigma(k)] as tf32 + |x|^2 partials ----
    {
        const int p  = tid & 127;
        const int hf = tid >> 7;
        float ss = 0.f;
        #pragma unroll
        for (int kk = 0; kk < 64; kk++) {
            int k = hf * 64 + kk;
            float v = stg[k * 128 + p];
            ss += v * v;
            xs[p * STRIDE + sigma(k)] = to_tf32(v);
        }
        red[tid] = ss;
    }
    __syncthreads();
    if (tid < 128) rs[tid] = 1.0f / fmaxf(sqrtf(red[tid] + red[tid + 128]), 1e-12f);

    // ---- Kick off async copies of proto chunks 0 and 1 ----
    #pragma unroll
    for (int c2 = 0; c2 < 2; c2++) {
        const uint32_t* src = g_PT + c2 * 16384;
        #pragma unroll
        for (int i2 = 0; i2 < 16; i2++) {
            int i = i2 * 256 + tid;
            int row = i >> 5, c16 = i & 31;
            cpa16(ptb[c2] + (uint32_t)(row * STRIDE + c16 * 4) * 4u,
                  src + row * 128 + c16 * 4);
        }
        CP_COMMIT();
    }

    const int cw = wid * 16;          // warp's class base
    const int c0 = cw + gq;           // this thread's classes: c0, c0+8
    float mn[16][4];                  // min over negatives, [ntile][frag elem]

    for (int cc = 0; cc < 4; cc++) {
        if (cc < 3) { CP_WAIT(1); } else { CP_WAIT(0); }
        __syncthreads();

        // ---- GEMM: 16 k-steps x 16 n-tiles of m16n8k8 tf32 ----
        const uint32_t* pb = pt[cc & 1];
        float acc[16][4];
        #pragma unroll
        for (int t = 0; t < 16; t++)
            acc[t][0] = acc[t][1] = acc[t][2] = acc[t][3] = 0.f;

        #pragma unroll
        for (int s = 0; s < 16; s++) {
            const int colb = s * 8 + 2 * jj;
            uint2 a01 = *(const uint2*)(pb + (cw + gq) * STRIDE + colb);
            uint2 a23 = *(const uint2*)(pb + (cw + gq + 8) * STRIDE + colb);
            #pragma unroll
            for (int t = 0; t < 16; t++) {
                uint2 bv = *(const uint2*)(xs + (t * 8 + gq) * STRIDE + colb);
                mma8(acc[t], a01, a23, bv);
            }
        }

        if (cc < 3) {
            // ---- Negatives: distances_neg + thread-local running min ----
            #pragma unroll
            for (int t = 0; t < 16; t++) {
                const int px0 = t * 8 + 2 * jj;
                float2 rv = *(const float2*)(rs + px0);
                float d00 = sqrtf(fmaxf(2.f - 2.f * acc[t][0] * rv.x, 1e-12f));
                float d01 = sqrtf(fmaxf(2.f - 2.f * acc[t][1] * rv.y, 1e-12f));
                float d10 = sqrtf(fmaxf(2.f - 2.f * acc[t][2] * rv.x, 1e-12f));
                float d11 = sqrtf(fmaxf(2.f - 2.f * acc[t][3] * rv.y, 1e-12f));
                if (cc == 0) {
                    mn[t][0] = d00; mn[t][1] = d01; mn[t][2] = d10; mn[t][3] = d11;
                } else {
                    mn[t][0] = fminf(mn[t][0], d00); mn[t][1] = fminf(mn[t][1], d01);
                    mn[t][2] = fminf(mn[t][2], d10); mn[t][3] = fminf(mn[t][3], d11);
                }
                size_t base = 33554432u
                    + ((size_t)(b * 128 + c0) * 3 + cc) * 16384 + hw0 + px0;
                __stcs((float2*)(out + base), make_float2(d00, d01));
                __stcs((float2*)(out + base + (size_t)8 * 3 * 16384),
                       make_float2(d10, d11));
            }
        } else {
            // ---- Positives: distances, probs_ori, q; class-sum; cls_score ----
            #pragma unroll
            for (int t = 0; t < 16; t++) {
                const int px0 = t * 8 + 2 * jj;
                float2 rv = *(const float2*)(rs + px0);
                float dst[4], ev[4], pr[4];
                #pragma unroll
                for (int e = 0; e < 4; e++) {
                    float rsp = (e & 1) ? rv.y : rv.x;
                    float m  = fmaxf(2.f - 2.f * acc[t][e] * rsp, 1e-12f);
                    float d  = sqrtf(m);
                    float e1 = __expf(-m);
                    float tv = d + 0.3f * (2.f - mn[t][e]);
                    float p1 = __expf(-2.f * tv * tv);
                    dst[e] = d; ev[e] = e1; pr[e] = p1;
                    acc[t][e] = e1 * p1;                 // q, reuse acc
                }
                size_t base0 = (size_t)(b * 128 + c0) * 16384 + hw0 + px0;
                size_t base1 = base0 + (size_t)8 * 16384;
                __stcs((float2*)(out + 16777216u + base0), make_float2(dst[0], dst[1]));
                __stcs((float2*)(out + 16777216u + base1), make_float2(dst[2], dst[3]));
                __stcs((float2*)(out + 83886080u + base0),
                       make_float2(ev[0] * ev[0], ev[1] * ev[1]));
                __stcs((float2*)(out + 83886080u + base1),
                       make_float2(ev[2] * ev[2], ev[3] * ev[3]));
                // per-px sum of pr over this warp's 16 classes
                float p0 = pr[0] + pr[2], p1 = pr[1] + pr[3];
                p0 += __shfl_xor_sync(~0u, p0, 4);  p1 += __shfl_xor_sync(~0u, p1, 4);
                p0 += __shfl_xor_sync(~0u, p0, 8);  p1 += __shfl_xor_sync(~0u, p1, 8);
                p0 += __shfl_xor_sync(~0u, p0, 16); p1 += __shfl_xor_sync(~0u, p1, 16);
                if (gq == 0) *(float2*)(psm + wid * 128 + px0) = make_float2(p0, p1);
            }
            __syncthreads();
            if (tid < 128) {
                float s = 0.f;
                #pragma unroll
                for (int w = 0; w < 8; w++) s += psm[w * 128 + tid];
                rs[tid] = 1.f / s;          // rs reused as inv (all reads done)
            }
            __syncthreads();
            #pragma unroll
            for (int t = 0; t < 16; t++) {
                const int px0 = t * 8 + 2 * jj;
                float2 iv = *(const float2*)(rs + px0);
                size_t base0 = (size_t)(b * 128 + c0) * 16384 + hw0 + px0;
                __stcs((float2*)(out + base0),
                       make_float2(acc[t][0] * iv.x, acc[t][1] * iv.y));
                __stcs((float2*)(out + base0 + (size_t)8 * 16384),
                       make_float2(acc[t][2] * iv.x, acc[t][3] * iv.y));
            }
        }

        __syncthreads();   // all warps done reading pt[cc&1] before refill
        if (cc < 2) {
            const uint32_t* src = g_PT + (cc + 2) * 16384;
            #pragma unroll
            for (int i2 = 0; i2 < 16; i2++) {
                int i = i2 * 256 + tid;
                int row = i >> 5, c16 = i & 31;
                cpa16(ptb[cc & 1] + (uint32_t)(row * STRIDE + c16 * 4) * 4u,
                      src + row * 128 + c16 * 4);
            }
            CP_COMMIT();
        }
    }
}

// ---------------------------------------------------------------------------
extern "C" void kernel_launch(void* const* d_in, const int* in_sizes, int n_in,
                              void* d_out, int out_size) {
    const float* x    = (const float*)d_in[0];
    const float* reps = (const float*)d_in[1];
    const float* fcw  = (const float*)d_in[2];
    const float* fcb  = (const float*)d_in[3];
    float* out = (float*)d_out;

    const int smem = 53632 * (int)sizeof(float);   // 214528 B
    cudaFuncSetAttribute(dml_main, cudaFuncAttributeMaxDynamicSharedMemorySize, smem);

    dml_prep<<<128, 128>>>(reps, fcw, fcb);
    dml_main<<<1024, 256, smem>>>(x, out);
}

// round 10
// speedup vs baseline: 3.3671x; 1.0457x over previous
#include <cuda_runtime.h>
#include <cstdint>

// Problem constants:
//   x: [8, 128, 128, 128]  (B, D, H, W), HW = 16384, NPIX = 131072
//   C = 128, M = 1, NEG = 3  -> 512 prototypes total
// Output tuple flattened:
//   cls_score     @ 0         (16777216)
//   distances     @ 16777216  (16777216)
//   distances_neg @ 33554432  (50331648)
//   probs_ori     @ 83886080  (16777216)

typedef unsigned long long ull;

// Prototypes as tf32 bits, sigma-permuted within each row:
// g_PT[chunk*16384 + class*128 + sigma(k)], chunks 0..2 = negs, 3 = positives.
__device__ __align__(16) uint32_t g_PT[4 * 128 * 128];

// k-permutation within each 8-block: pos = 2*(k&3) + ((k>>2)&1)
// => (c, c+4) fragment pairs are adjacent -> single LDS.64 per fragment.
__device__ __forceinline__ int sigma(int k) {
    return (k >> 3) * 8 + 2 * (k & 3) + ((k >> 2) & 1);
}

__device__ __forceinline__ uint32_t to_tf32(float f) {
    uint32_t u; asm("cvt.rna.tf32.f32 %0, %1;" : "=r"(u) : "f"(f)); return u;
}

__device__ __forceinline__ uint32_t smem_u32(const void* p) {
    uint32_t a;
    asm("{ .reg .u64 t; cvta.to.shared.u64 t, %1; cvt.u32.u64 %0, t; }" : "=r"(a) : "l"(p));
    return a;
}

__device__ __forceinline__ void cpa16(uint32_t dst, const void* src) {
    asm volatile("cp.async.ca.shared.global [%0], [%1], 16;" :: "r"(dst), "l"(src) : "memory");
}
#define CP_COMMIT() asm volatile("cp.async.commit_group;" ::: "memory")
#define CP_WAIT(n)  asm volatile("cp.async.wait_group %0;" :: "n"(n) : "memory")

// tf32 mma m16n8k8 (sm_80+, valid at base sm_103 target).
__device__ __forceinline__ void mma8(float* d, uint2 a01, uint2 a23, uint2 bv) {
    asm volatile(
        "mma.sync.aligned.m16n8k8.row.col.f32.tf32.tf32.f32 "
        "{%0,%1,%2,%3}, {%4,%5,%6,%7}, {%8,%9}, {%0,%1,%2,%3};"
        : "+f"(d[0]), "+f"(d[1]), "+f"(d[2]), "+f"(d[3])
        : "r"(a01.x), "r"(a23.x), "r"(a01.y), "r"(a23.y), "r"(bv.x), "r"(bv.y));
}

// ---------------------------------------------------------------------------
// Prep: normalize reps, build negatives, store tf32 sigma-permuted.
// ---------------------------------------------------------------------------
__global__ void dml_prep(const float* __restrict__ reps_w,
                         const float* __restrict__ fc_w,
                         const float* __restrict__ fc_b) {
    __shared__ float repn[128];
    __shared__ float red[128];
    const int c = blockIdx.x;
    const int d = threadIdx.x;

    float w = reps_w[c * 128 + d];
    red[d] = w * w;
    __syncthreads();
    for (int s = 64; s > 0; s >>= 1) { if (d < s) red[d] += red[d + s]; __syncthreads(); }
    float S = red[0];
    __syncthreads();
    float rn = w / fmaxf(sqrtf(S), 1e-12f);
    repn[d] = rn;
    g_PT[3 * 16384 + c * 128 + sigma(d)] = to_tf32(rn);
    __syncthreads();

    for (int n = 0; n < 3; n++) {
        const float* wr = fc_w + (size_t)(n * 128 + d) * 128;
        float a = fc_b[n * 128 + d];
        #pragma unroll 8
        for (int k = 0; k < 128; k++) a += repn[k] * wr[k];
        float v = a + rn;
        red[d] = v * v;
        __syncthreads();
        for (int s = 64; s > 0; s >>= 1) { if (d < s) red[d] += red[d + s]; __syncthreads(); }
        float S2 = red[0];
        __syncthreads();
        g_PT[n * 16384 + c * 128 + sigma(d)] = to_tf32(v / fmaxf(sqrtf(S2), 1e-12f));
    }
}

// ---------------------------------------------------------------------------
// Main: tf32 mma.sync GEMM [128px x 128k] x [128k x 512proto] + fused epilogue.
// grid = 1024, block = 512 (16 warps), 1 CTA/SM (smem-bound).
// Warp tile per chunk: 16 classes x 64 px (8 n-tiles of m16n8k8).
//   wid>>1 = class group (16 classes), wid&1 = pixel half (64 px).
// smem (floats, STRIDE 136 rows):
//   xs  [0, 17408)        x in tf32, [px][sigma(k)]
//   pt0 [17408, 34816)    proto chunk buffer 0 (also raw-x staging)
//   pt1 [34816, 52224)    proto chunk buffer 1
//   red [52224, 52736) | rs [52736, 52864) | psm [52864, 53888)
// total 53888 floats = 215552 B.
// ---------------------------------------------------------------------------
#define STRIDE 136

__global__ __launch_bounds__(512, 1)
void dml_main(const float* __restrict__ x, float* __restrict__ out) {
    extern __shared__ float sm[];
    uint32_t* xs  = (uint32_t*)sm;
    float*    stg = sm + 17408;                      // raw x staging (pt0 alias)
    const uint32_t* pt[2] = { (const uint32_t*)(sm + 17408),
                              (const uint32_t*)(sm + 34816) };
    float* red = sm + 52224;    // 512
    float* rs  = sm + 52736;    // 128
    float* psm = sm + 52864;    // 1024
    const uint32_t sbase = smem_u32(sm);
    const uint32_t ptb[2] = { sbase + 17408u * 4u, sbase + 34816u * 4u };

    const int tid  = threadIdx.x;
    const int wid  = tid >> 5;
    const int lane = tid & 31;
    const int gq   = lane >> 2;     // group id (class row / B n-index)
    const int jj   = lane & 3;      // thread-in-group (k index / C px pair)
    const int b    = blockIdx.x >> 7;
    const int hw0  = (blockIdx.x & 127) << 7;

    // ---- Stage raw x [128k][128px] (coalesced float4) ----
    {
        const float4* xb4 = (const float4*)(x + ((size_t)b * 128) * 16384 + hw0);
        float4* st4 = (float4*)stg;
        #pragma unroll
        for (int it = 0; it < 8; it++) {
            int i = it * 512 + tid;
            st4[i] = xb4[(i >> 5) * 4096 + (i & 31)];
        }
    }
    __syncthreads();

    // ---- Transpose to xs[px][sigma(k)] as tf32 + |x|^2 partials ----
    {
        const int p  = tid & 127;
        const int qr = tid >> 7;                 // k-quarter (32 k each)
        float ss = 0.f;
        #pragma unroll
        for (int kk = 0; kk < 32; kk++) {
            int k = qr * 32 + kk;
            float v = stg[k * 128 + p];
            ss += v * v;
            xs[p * STRIDE + sigma(k)] = to_tf32(v);
        }
        red[tid] = ss;
    }
    __syncthreads();
    if (tid < 128)
        rs[tid] = 1.0f / fmaxf(sqrtf(red[tid] + red[tid + 128] +
                                     red[tid + 256] + red[tid + 384]), 1e-12f);

    // ---- Kick off async copies of proto chunks 0 and 1 ----
    #pragma unroll
    for (int c2 = 0; c2 < 2; c2++) {
        const uint32_t* src = g_PT + c2 * 16384;
        #pragma unroll
        for (int i2 = 0; i2 < 8; i2++) {
            int i = i2 * 512 + tid;
            int row = i >> 5, c16 = i & 31;
            cpa16(ptb[c2] + (uint32_t)(row * STRIDE + c16 * 4) * 4u,
                  src + row * 128 + c16 * 4);
        }
        CP_COMMIT();
    }

    const int cw  = (wid >> 1) * 16;   // warp's class base (8 groups)
    const int pxh = (wid & 1) * 64;    // warp's pixel half
    const int c0  = cw + gq;           // this thread's classes: c0, c0+8
    float mn[8][4];                    // min over negatives, [ntile][frag elem]

    for (int cc = 0; cc < 4; cc++) {
        if (cc < 3) { CP_WAIT(1); } else { CP_WAIT(0); }
        __syncthreads();

        // ---- GEMM: 16 k-steps x 8 n-tiles of m16n8k8 tf32 ----
        const uint32_t* pb = pt[cc & 1];
        float acc[8][4];
        #pragma unroll
        for (int t = 0; t < 8; t++)
            acc[t][0] = acc[t][1] = acc[t][2] = acc[t][3] = 0.f;

        #pragma unroll
        for (int s = 0; s < 16; s++) {
            const int colb = s * 8 + 2 * jj;
            uint2 a01 = *(const uint2*)(pb + (cw + gq) * STRIDE + colb);
            uint2 a23 = *(const uint2*)(pb + (cw + gq + 8) * STRIDE + colb);
            #pragma unroll
            for (int t = 0; t < 8; t++) {
                uint2 bv = *(const uint2*)(xs + (pxh + t * 8 + gq) * STRIDE + colb);
                mma8(acc[t], a01, a23, bv);
            }
        }

        if (cc < 3) {
            // ---- Negatives: distances_neg + thread-local running min ----
            #pragma unroll
            for (int t = 0; t < 8; t++) {
                const int px0 = pxh + t * 8 + 2 * jj;
                float2 rv = *(const float2*)(rs + px0);
                float d00 = sqrtf(fmaxf(2.f - 2.f * acc[t][0] * rv.x, 1e-12f));
                float d01 = sqrtf(fmaxf(2.f - 2.f * acc[t][1] * rv.y, 1e-12f));
                float d10 = sqrtf(fmaxf(2.f - 2.f * acc[t][2] * rv.x, 1e-12f));
                float d11 = sqrtf(fmaxf(2.f - 2.f * acc[t][3] * rv.y, 1e-12f));
                if (cc == 0) {
                    mn[t][0] = d00; mn[t][1] = d01; mn[t][2] = d10; mn[t][3] = d11;
                } else {
                    mn[t][0] = fminf(mn[t][0], d00); mn[t][1] = fminf(mn[t][1], d01);
                    mn[t][2] = fminf(mn[t][2], d10); mn[t][3] = fminf(mn[t][3], d11);
                }
                size_t base = 33554432u
                    + ((size_t)(b * 128 + c0) * 3 + cc) * 16384 + hw0 + px0;
                __stcs((float2*)(out + base), make_float2(d00, d01));
                __stcs((float2*)(out + base + (size_t)8 * 3 * 16384),
                       make_float2(d10, d11));
            }
        } else {
            // ---- Positives: distances, probs_ori, q; class-sum; cls_score ----
            #pragma unroll
            for (int t = 0; t < 8; t++) {
                const int px0 = pxh + t * 8 + 2 * jj;
                float2 rv = *(const float2*)(rs + px0);
                float dst[4], ev[4], pr[4];
                #pragma unroll
                for (int e = 0; e < 4; e++) {
                    float rsp = (e & 1) ? rv.y : rv.x;
                    float m  = fmaxf(2.f - 2.f * acc[t][e] * rsp, 1e-12f);
                    float d  = sqrtf(m);
                    float e1 = __expf(-m);
                    float tv = d + 0.3f * (2.f - mn[t][e]);
                    float p1 = __expf(-2.f * tv * tv);
                    dst[e] = d; ev[e] = e1; pr[e] = p1;
                    acc[t][e] = e1 * p1;                 // q, reuse acc
                }
                size_t base0 = (size_t)(b * 128 + c0) * 16384 + hw0 + px0;
                size_t base1 = base0 + (size_t)8 * 16384;
                __stcs((float2*)(out + 16777216u + base0), make_float2(dst[0], dst[1]));
                __stcs((float2*)(out + 16777216u + base1), make_float2(dst[2], dst[3]));
                __stcs((float2*)(out + 83886080u + base0),
                       make_float2(ev[0] * ev[0], ev[1] * ev[1]));
                __stcs((float2*)(out + 83886080u + base1),
                       make_float2(ev[2] * ev[2], ev[3] * ev[3]));
                // per-px sum of pr over this warp's 16 classes
                float p0 = pr[0] + pr[2], p1 = pr[1] + pr[3];
                p0 += __shfl_xor_sync(~0u, p0, 4);  p1 += __shfl_xor_sync(~0u, p1, 4);
                p0 += __shfl_xor_sync(~0u, p0, 8);  p1 += __shfl_xor_sync(~0u, p1, 8);
                p0 += __shfl_xor_sync(~0u, p0, 16); p1 += __shfl_xor_sync(~0u, p1, 16);
                if (gq == 0)
                    *(float2*)(psm + (wid >> 1) * 128 + px0) = make_float2(p0, p1);
            }
            __syncthreads();
            if (tid < 128) {
                float s = 0.f;
                #pragma unroll
                for (int w = 0; w < 8; w++) s += psm[w * 128 + tid];
                rs[tid] = 1.f / s;          // rs reused as inv (all reads done)
            }
            __syncthreads();
            #pragma unroll
            for (int t = 0; t < 8; t++) {
                const int px0 = pxh + t * 8 + 2 * jj;
                float2 iv = *(const float2*)(rs + px0);
                size_t base0 = (size_t)(b * 128 + c0) * 16384 + hw0 + px0;
                __stcs((float2*)(out + base0),
                       make_float2(acc[t][0] * iv.x, acc[t][1] * iv.y));
                __stcs((float2*)(out + base0 + (size_t)8 * 16384),
                       make_float2(acc[t][2] * iv.x, acc[t][3] * iv.y));
            }
        }

        __syncthreads();   // all warps done reading pt[cc&1] before refill
        if (cc < 2) {
            const uint32_t* src = g_PT + (cc + 2) * 16384;
            #pragma unroll
            for (int i2 = 0; i2 < 8; i2++) {
                int i = i2 * 512 + tid;
                int row = i >> 5, c16 = i & 31;
                cpa16(ptb[cc & 1] + (uint32_t)(row * STRIDE + c16 * 4) * 4u,
                      src + row * 128 + c16 * 4);
            }
            CP_COMMIT();
        }
    }
}

// ---------------------------------------------------------------------------
extern "C" void kernel_launch(void* const* d_in, const int* in_sizes, int n_in,
                              void* d_out, int out_size) {
    const float* x    = (const float*)d_in[0];
    const float* reps = (const float*)d_in[1];
    const float* fcw  = (const float*)d_in[2];
    const float* fcb  = (const float*)d_in[3];
    float* out = (float*)d_out;

    const int smem = 53888 * (int)sizeof(float);   // 215552 B
    cudaFuncSetAttribute(dml_main, cudaFuncAttributeMaxDynamicSharedMemorySize, smem);

    dml_prep<<<128, 128>>>(reps, fcw, fcb);
    dml_main<<<1024, 512, smem>>>(x, out);
}

// round 11
// speedup vs baseline: 3.4790x; 1.0332x over previous
#include <cuda_runtime.h>
#include <cstdint>

// Problem constants:
//   x: [8, 128, 128, 128]  (B, D, H, W), HW = 16384, NPIX = 131072
//   C = 128, M = 1, NEG = 3  -> 512 prototypes total
// Output tuple flattened:
//   cls_score     @ 0         (16777216)
//   distances     @ 16777216  (16777216)
//   distances_neg @ 33554432  (50331648)
//   probs_ori     @ 83886080  (16777216)

typedef unsigned long long ull;

// Prototypes as tf32 bits, sigma-permuted within each row:
// g_PT[chunk*16384 + class*128 + sigma(k)], chunks 0..2 = negs, 3 = positives.
__device__ __align__(16) uint32_t g_PT[4 * 128 * 128];

// k-permutation within each 8-block: pos = 2*(k&3) + ((k>>2)&1)
// => mma fragment pairs (k, k+4) are adjacent -> one LDS.64 per fragment.
__device__ __forceinline__ int sigma(int k) {
    return (k >> 3) * 8 + 2 * (k & 3) + ((k >> 2) & 1);
}

__device__ __forceinline__ uint32_t to_tf32(float f) {
    uint32_t u; asm("cvt.rna.tf32.f32 %0, %1;" : "=r"(u) : "f"(f)); return u;
}

__device__ __forceinline__ uint32_t smem_u32(const void* p) {
    uint32_t a;
    asm("{ .reg .u64 t; cvta.to.shared.u64 t, %1; cvt.u32.u64 %0, t; }" : "=r"(a) : "l"(p));
    return a;
}

__device__ __forceinline__ void cpa16(uint32_t dst, const void* src) {
    asm volatile("cp.async.ca.shared.global [%0], [%1], 16;" :: "r"(dst), "l"(src) : "memory");
}
#define CP_COMMIT() asm volatile("cp.async.commit_group;" ::: "memory")
#define CP_WAIT(n)  asm volatile("cp.async.wait_group %0;" :: "n"(n) : "memory")

// tf32 mma m16n8k8 (sm_80+, valid at base sm_103 target).
__device__ __forceinline__ void mma8(float* d, uint2 a01, uint2 a23, uint2 bv) {
    asm volatile(
        "mma.sync.aligned.m16n8k8.row.col.f32.tf32.tf32.f32 "
        "{%0,%1,%2,%3}, {%4,%5,%6,%7}, {%8,%9}, {%0,%1,%2,%3};"
        : "+f"(d[0]), "+f"(d[1]), "+f"(d[2]), "+f"(d[3])
        : "r"(a01.x), "r"(a23.x), "r"(a01.y), "r"(a23.y), "r"(bv.x), "r"(bv.y));
}

// ---------------------------------------------------------------------------
// Prep: normalize reps, build negatives, store tf32 sigma-permuted.
// ---------------------------------------------------------------------------
__global__ void dml_prep(const float* __restrict__ reps_w,
                         const float* __restrict__ fc_w,
                         const float* __restrict__ fc_b) {
    __shared__ float repn[128];
    __shared__ float red[128];
    const int c = blockIdx.x;
    const int d = threadIdx.x;

    float w = reps_w[c * 128 + d];
    red[d] = w * w;
    __syncthreads();
    for (int s = 64; s > 0; s >>= 1) { if (d < s) red[d] += red[d + s]; __syncthreads(); }
    float S = red[0];
    __syncthreads();
    float rn = w / fmaxf(sqrtf(S), 1e-12f);
    repn[d] = rn;
    g_PT[3 * 16384 + c * 128 + sigma(d)] = to_tf32(rn);
    __syncthreads();

    for (int n = 0; n < 3; n++) {
        const float* wr = fc_w + (size_t)(n * 128 + d) * 128;
        float a = fc_b[n * 128 + d];
        #pragma unroll 8
        for (int k = 0; k < 128; k++) a += repn[k] * wr[k];
        float v = a + rn;
        red[d] = v * v;
        __syncthreads();
        for (int s = 64; s > 0; s >>= 1) { if (d < s) red[d] += red[d + s]; __syncthreads(); }
        float S2 = red[0];
        __syncthreads();
        g_PT[n * 16384 + c * 128 + sigma(d)] = to_tf32(v / fmaxf(sqrtf(S2), 1e-12f));
    }
}

// ---------------------------------------------------------------------------
// Main: tf32 mma.sync GEMM [64px x 128k] x [128k x 512proto] + fused epilogue.
// grid = 2048 (8 b * 256 px-tiles of 64), block = 256 (8 warps), 2 CTAs/SM.
// Warp tile per chunk: 16 classes x 64 px (8 n-tiles of m16n8k8).
// Explicit register double-buffer on fragments; immediate-offset LDS.
// smem (floats, STRIDE 136 rows):
//   xs  [0, 8704)        x in tf32, [px][sigma(k)]
//   pt  [8704, 26112)    proto chunk buffer (single, reloaded per chunk)
//   red [26112, 26368) | rs [26368, 26432) | psm [26432, 26944)
// total 26944 floats = 107776 B -> 2 CTAs/SM (215552 <= 227KB).
// ---------------------------------------------------------------------------
#define STRIDE 136

__global__ __launch_bounds__(256, 2)
void dml_main(const float* __restrict__ x, float* __restrict__ out) {
    extern __shared__ float sm[];
    uint32_t* xs = (uint32_t*)sm;
    uint32_t* pt = (uint32_t*)(sm + 8704);
    float* red = sm + 26112;    // 256
    float* rs  = sm + 26368;    // 64
    float* psm = sm + 26432;    // 512
    const uint32_t sbase = smem_u32(sm);
    const uint32_t ptb   = sbase + 8704u * 4u;

    const int tid  = threadIdx.x;
    const int wid  = tid >> 5;
    const int lane = tid & 31;
    const int gq   = lane >> 2;     // group id (class row / B n-index)
    const int jj   = lane & 3;      // thread-in-group
    const int b    = blockIdx.x >> 8;
    const int hw0  = (blockIdx.x & 255) << 6;

    // ---- Direct transposed load: gmem x[k][p] -> xs[p][sigma(k)] (tf32) ----
    {
        const float* xg = x + ((size_t)b * 128) * 16384 + hw0;
        const int p  = tid & 63;
        const int kq = tid >> 6;                 // k-quarter (32 k each)
        float ss = 0.f;
        #pragma unroll
        for (int kk = 0; kk < 32; kk++) {
            int k = kq * 32 + kk;
            float v = xg[(size_t)k * 16384 + p];   // 128B/warp coalesced
            ss += v * v;
            xs[p * STRIDE + sigma(k)] = to_tf32(v);
        }
        red[tid] = ss;
    }
    __syncthreads();
    if (tid < 64)
        rs[tid] = 1.0f / fmaxf(sqrtf(red[tid] + red[tid + 64] +
                                     red[tid + 128] + red[tid + 192]), 1e-12f);

    const int cw = wid * 16;           // warp's class base
    const int c0 = cw + gq;            // this thread's classes: c0, c0+8
    float mn[8][4];                    // min over negatives, [ntile][frag elem]

    for (int cc = 0; cc < 4; cc++) {
        // ---- Load proto chunk cc into the single pt buffer ----
        __syncthreads();               // previous chunk's reads done
        {
            const uint32_t* src = g_PT + cc * 16384;
            #pragma unroll
            for (int i2 = 0; i2 < 16; i2++) {
                int i = i2 * 256 + tid;
                int row = i >> 5, c16 = i & 31;
                cpa16(ptb + (uint32_t)(row * STRIDE + c16 * 4) * 4u,
                      src + row * 128 + c16 * 4);
            }
        }
        CP_COMMIT();
        CP_WAIT(0);
        __syncthreads();

        // ---- GEMM: 16 k-steps x 8 n-tiles, register double-buffered ----
        const uint32_t* ap = pt + (cw + gq) * STRIDE + 2 * jj;
        const uint32_t* bp = xs + gq * STRIDE + 2 * jj;

        float acc[8][4];
        #pragma unroll
        for (int t = 0; t < 8; t++)
            acc[t][0] = acc[t][1] = acc[t][2] = acc[t][3] = 0.f;

        uint2 a01 = *(const uint2*)(ap);
        uint2 a23 = *(const uint2*)(ap + 8 * STRIDE);
        uint2 bv[8];
        #pragma unroll
        for (int t = 0; t < 8; t++)
            bv[t] = *(const uint2*)(bp + t * 8 * STRIDE);

        #pragma unroll
        for (int s = 0; s < 16; s++) {
            uint2 na01, na23, nbv[8];
            if (s < 15) {
                const int o = (s + 1) * 8;
                na01 = *(const uint2*)(ap + o);
                na23 = *(const uint2*)(ap + 8 * STRIDE + o);
                #pragma unroll
                for (int t = 0; t < 8; t++)
                    nbv[t] = *(const uint2*)(bp + t * 8 * STRIDE + o);
            }
            #pragma unroll
            for (int t = 0; t < 8; t++) mma8(acc[t], a01, a23, bv[t]);
            if (s < 15) {
                a01 = na01; a23 = na23;
                #pragma unroll
                for (int t = 0; t < 8; t++) bv[t] = nbv[t];
            }
        }

        if (cc < 3) {
            // ---- Negatives: distances_neg + thread-local running min ----
            #pragma unroll
            for (int t = 0; t < 8; t++) {
                const int px0 = t * 8 + 2 * jj;
                float2 rv = *(const float2*)(rs + px0);
                float d00 = sqrtf(fmaxf(2.f - 2.f * acc[t][0] * rv.x, 1e-12f));
                float d01 = sqrtf(fmaxf(2.f - 2.f * acc[t][1] * rv.y, 1e-12f));
                float d10 = sqrtf(fmaxf(2.f - 2.f * acc[t][2] * rv.x, 1e-12f));
                float d11 = sqrtf(fmaxf(2.f - 2.f * acc[t][3] * rv.y, 1e-12f));
                if (cc == 0) {
                    mn[t][0] = d00; mn[t][1] = d01; mn[t][2] = d10; mn[t][3] = d11;
                } else {
                    mn[t][0] = fminf(mn[t][0], d00); mn[t][1] = fminf(mn[t][1], d01);
                    mn[t][2] = fminf(mn[t][2], d10); mn[t][3] = fminf(mn[t][3], d11);
                }
                size_t base = 33554432u
                    + ((size_t)(b * 128 + c0) * 3 + cc) * 16384 + hw0 + px0;
                __stcs((float2*)(out + base), make_float2(d00, d01));
                __stcs((float2*)(out + base + (size_t)8 * 3 * 16384),
                       make_float2(d10, d11));
            }
        } else {
            // ---- Positives: distances, probs_ori, q; class-sum; cls_score ----
            #pragma unroll
            for (int t = 0; t < 8; t++) {
                const int px0 = t * 8 + 2 * jj;
                float2 rv = *(const float2*)(rs + px0);
                float dst[4], ev[4], pr[4];
                #pragma unroll
                for (int e = 0; e < 4; e++) {
                    float rsp = (e & 1) ? rv.y : rv.x;
                    float m  = fmaxf(2.f - 2.f * acc[t][e] * rsp, 1e-12f);
                    float d  = sqrtf(m);
                    float e1 = __expf(-m);
                    float tv = d + 0.3f * (2.f - mn[t][e]);
                    float p1 = __expf(-2.f * tv * tv);
                    dst[e] = d; ev[e] = e1; pr[e] = p1;
                    acc[t][e] = e1 * p1;                 // q, reuse acc
                }
                size_t base0 = (size_t)(b * 128 + c0) * 16384 + hw0 + px0;
                size_t base1 = base0 + (size_t)8 * 16384;
                __stcs((float2*)(out + 16777216u + base0), make_float2(dst[0], dst[1]));
                __stcs((float2*)(out + 16777216u + base1), make_float2(dst[2], dst[3]));
                __stcs((float2*)(out + 83886080u + base0),
                       make_float2(ev[0] * ev[0], ev[1] * ev[1]));
                __stcs((float2*)(out + 83886080u + base1),
                       make_float2(ev[2] * ev[2], ev[3] * ev[3]));
                // per-px sum of pr over this warp's 16 classes
                float p0 = pr[0] + pr[2], p1 = pr[1] + pr[3];
                p0 += __shfl_xor_sync(~0u, p0, 4);  p1 += __shfl_xor_sync(~0u, p1, 4);
                p0 += __shfl_xor_sync(~0u, p0, 8);  p1 += __shfl_xor_sync(~0u, p1, 8);
                p0 += __shfl_xor_sync(~0u, p0, 16); p1 += __shfl_xor_sync(~0u, p1, 16);
                if (gq == 0)
                    *(float2*)(psm + wid * 64 + px0) = make_float2(p0, p1);
            }
            __syncthreads();
            if (tid < 64) {
                float s = 0.f;
                #pragma unroll
                for (int w = 0; w < 8; w++) s += psm[w * 64 + tid];
                rs[tid] = 1.f / s;          // rs reused as inv (all reads done)
            }
            __syncthreads();
            #pragma unroll
            for (int t = 0; t < 8; t++) {
                const int px0 = t * 8 + 2 * jj;
                float2 iv = *(const float2*)(rs + px0);
                size_t base0 = (size_t)(b * 128 + c0) * 16384 + hw0 + px0;
                __stcs((float2*)(out + base0),
                       make_float2(acc[t][0] * iv.x, acc[t][1] * iv.y));
                __stcs((float2*)(out + base0 + (size_t)8 * 16384),
                       make_float2(acc[t][2] * iv.x, acc[t][3] * iv.y));
            }
        }
    }
}

// ---------------------------------------------------------------------------
extern "C" void kernel_launch(void* const* d_in, const int* in_sizes, int n_in,
                              void* d_out, int out_size) {
    const float* x    = (const float*)d_in[0];
    const float* reps = (const float*)d_in[1];
    const float* fcw  = (const float*)d_in[2];
    const float* fcb  = (const float*)d_in[3];
    float* out = (float*)d_out;

    const int smem = 26944 * (int)sizeof(float);   // 107776 B
    cudaFuncSetAttribute(dml_main, cudaFuncAttributeMaxDynamicSharedMemorySize, smem);

    dml_prep<<<128, 128>>>(reps, fcw, fcb);
    dml_main<<<2048, 256, smem>>>(x, out);
}